// round 1
// baseline (speedup 1.0000x reference)
#include <cuda_runtime.h>

// Problem constants (fixed by the dataset): B=8, S=2048 -> 16384 tokens,
// D=1024, F=64, TOPK=8. Three GEMMs stacked as NOUT=192 outputs per token.
#define DD    1024
#define FF    64
#define TOPKK 8
#define TM    64     // tokens per block
#define KB    32     // k-chunk
#define NOUT  192    // 3*F stacked outputs
#define XROW  33     // padded x-tile row (conflict-free broadcast reads)
#define WROW  200    // padded weight-tile row (16B-aligned, conflict-free stores)

__global__ __launch_bounds__(256, 2)
void fused_gate_kernel(const float* __restrict__ x,
                       const float* __restrict__ Wt,
                       const float* __restrict__ bt,
                       const float* __restrict__ Wf,
                       const float* __restrict__ bf,
                       const float* __restrict__ Wg,
                       const float* __restrict__ bg,
                       const float* __restrict__ alpha,
                       float* __restrict__ out)
{
    // 48KB static smem, used as a union:
    //   main loop:  xs[TM][XROW] (2112 f) + ws[KB][WROW] (6400 f) = 8512 floats
    //   epilogue:   epi[TM][NOUT] = 12288 floats (49152 B)
    __shared__ float smem[12288];
    float* xs = smem;
    float* ws = smem + TM * XROW;

    const int tid  = threadIdx.x;
    const int r    = tid >> 4;      // 0..15 -> token group (4 tokens)
    const int c    = tid & 15;      // 0..15 -> output group (12 outputs)
    const int tok0 = blockIdx.x * TM;
    const int c12  = c * 12;
    const int t4   = r * 4;

    float acc[4][12];
    #pragma unroll
    for (int i = 0; i < 4; i++)
        #pragma unroll
        for (int j = 0; j < 12; j++) acc[i][j] = 0.f;

    for (int k0 = 0; k0 < DD; k0 += KB) {
        // ---- load x tile [TM][KB] (coalesced float4) ----
        #pragma unroll
        for (int p = tid; p < (TM * KB) / 4; p += 256) {
            int t  = p >> 3;            // KB/4 = 8 vec4 per token
            int kv = (p & 7) << 2;
            float4 v = *(const float4*)(x + (size_t)(tok0 + t) * DD + k0 + kv);
            float* dst = xs + t * XROW + kv;
            dst[0] = v.x; dst[1] = v.y; dst[2] = v.z; dst[3] = v.w;
        }
        // ---- W_top / W_feat tiles: [D,F] row-major, rows contiguous ----
        #pragma unroll
        for (int p = tid; p < (KB * FF) / 4; p += 256) {
            int kk = p >> 4;
            int fv = (p & 15) << 2;
            *(float4*)(ws + kk * WROW + fv)      = *(const float4*)(Wt + (size_t)(k0 + kk) * FF + fv);
            *(float4*)(ws + kk * WROW + FF + fv) = *(const float4*)(Wf + (size_t)(k0 + kk) * FF + fv);
        }
        // ---- W_gates [F,D]: transpose into ws[kk][128+f]; f-fast mapping
        //      gives conflict-free smem stores (f spans lanes) ----
        #pragma unroll
        for (int p = tid; p < (FF * KB) / 4; p += 256) {
            int f  = p & 63;
            int kv = (p >> 6) << 2;
            float4 g4 = *(const float4*)(Wg + (size_t)f * DD + k0 + kv);
            ws[(kv + 0) * WROW + 2 * FF + f] = g4.x;
            ws[(kv + 1) * WROW + 2 * FF + f] = g4.y;
            ws[(kv + 2) * WROW + 2 * FF + f] = g4.z;
            ws[(kv + 3) * WROW + 2 * FF + f] = g4.w;
        }
        __syncthreads();

        // ---- register-tiled FMA: 4 tokens x 12 outputs per thread ----
        #pragma unroll
        for (int kk = 0; kk < KB; ++kk) {
            float a0 = xs[(t4 + 0) * XROW + kk];
            float a1 = xs[(t4 + 1) * XROW + kk];
            float a2 = xs[(t4 + 2) * XROW + kk];
            float a3 = xs[(t4 + 3) * XROW + kk];
            const float* wrow = ws + kk * WROW + c12;
            float4 b0 = *(const float4*)(wrow);
            float4 b1 = *(const float4*)(wrow + 4);
            float4 b2 = *(const float4*)(wrow + 8);
            float bb[12] = {b0.x, b0.y, b0.z, b0.w,
                            b1.x, b1.y, b1.z, b1.w,
                            b2.x, b2.y, b2.z, b2.w};
            #pragma unroll
            for (int j = 0; j < 12; j++) {
                acc[0][j] = fmaf(a0, bb[j], acc[0][j]);
                acc[1][j] = fmaf(a1, bb[j], acc[1][j]);
                acc[2][j] = fmaf(a2, bb[j], acc[2][j]);
                acc[3][j] = fmaf(a3, bb[j], acc[3][j]);
            }
        }
        __syncthreads();
    }

    // ---- epilogue: transpose accumulators through smem ----
    float* epi = smem;
    #pragma unroll
    for (int i = 0; i < 4; i++)
        #pragma unroll
        for (int j = 0; j < 12; j++)
            epi[(t4 + i) * NOUT + c12 + j] = acc[i][j];
    __syncthreads();

    const float av = 1.f / (1.f + __expf(-alpha[0]));  // sigmoid(alpha)
    const int lane = tid & 31;
    const int wid  = tid >> 5;
    const unsigned FULLM = 0xffffffffu;
    const float NEGINF = __int_as_float(0xff800000);

    // one warp per token; each lane owns experts {lane, lane+32}
    for (int t = wid; t < TM; t += 8) {
        const float* row = epi + t * NOUT;
        float vt0 = row[lane]           + bt[lane];
        float vt1 = row[lane + 32]      + bt[lane + 32];
        float vf0 = row[FF + lane]      + bf[lane];
        float vf1 = row[FF + lane + 32] + bf[lane + 32];
        float g0  = 1.f / (1.f + __expf(-(row[2 * FF + lane]      + bg[lane])));
        float g1  = 1.f / (1.f + __expf(-(row[2 * FF + lane + 32] + bg[lane + 32])));

        // dense softmax branch: sum_f softmax(feat)_f * gate_f
        float m = fmaxf(vf0, vf1);
        #pragma unroll
        for (int o = 16; o; o >>= 1) m = fmaxf(m, __shfl_xor_sync(FULLM, m, o));
        float e0 = __expf(vf0 - m), e1 = __expf(vf1 - m);
        float fn = e0 * g0 + e1 * g1;
        float fd = e0 + e1;
        #pragma unroll
        for (int o = 16; o; o >>= 1) {
            fn += __shfl_xor_sync(FULLM, fn, o);
            fd += __shfl_xor_sync(FULLM, fd, o);
        }

        // top-8 branch: iterative warp-max selection (set-invariant vs top_k)
        bool r0 = false, r1 = false;
        float tn = 0.f, td = 0.f, vmax = 0.f;
        #pragma unroll
        for (int it = 0; it < TOPKK; ++it) {
            float c0 = r0 ? NEGINF : vt0;
            float c1 = r1 ? NEGINF : vt1;
            float cm = fmaxf(c0, c1);
            float m8 = cm;
            #pragma unroll
            for (int o = 16; o; o >>= 1) m8 = fmaxf(m8, __shfl_xor_sync(FULLM, m8, o));
            if (it == 0) vmax = m8;
            unsigned bal = __ballot_sync(FULLM, cm == m8);
            int owner = __ffs(bal) - 1;
            if (lane == owner) {
                if (!r0 && vt0 == m8) {
                    r0 = true;
                    float e = __expf(vt0 - vmax);
                    tn += e * g0; td += e;
                } else {
                    r1 = true;
                    float e = __expf(vt1 - vmax);
                    tn += e * g1; td += e;
                }
            }
        }
        #pragma unroll
        for (int o = 16; o; o >>= 1) {
            tn += __shfl_xor_sync(FULLM, tn, o);
            td += __shfl_xor_sync(FULLM, td, o);
        }

        if (lane == 0)
            out[tok0 + t] = av * (tn / td) + (1.f - av) * (fn / fd);
    }
}

extern "C" void kernel_launch(void* const* d_in, const int* in_sizes, int n_in,
                              void* d_out, int out_size) {
    const float* x  = (const float*)d_in[0];
    const float* Wt = (const float*)d_in[1];
    const float* bt = (const float*)d_in[2];
    const float* Wf = (const float*)d_in[3];
    const float* bf = (const float*)d_in[4];
    const float* Wg = (const float*)d_in[5];
    const float* bg = (const float*)d_in[6];
    const float* al = (const float*)d_in[7];
    float* out = (float*)d_out;
    const int ntok = out_size;  // B*S = 16384 (out is [B,S,1])
    fused_gate_kernel<<<ntok / TM, 256>>>(x, Wt, bt, Wf, bf, Wg, bg, al, out);
}

// round 2
// speedup vs baseline: 1.0011x; 1.0011x over previous
#include <cuda_runtime.h>

// Problem constants (fixed by the dataset): B=8, S=2048 -> 16384 tokens,
// D=1024, F=64, TOPK=8. Three GEMMs stacked as NOUT=192 outputs per token.
#define DD    1024
#define FF    64
#define TOPKK 8
#define TM    64     // tokens per block
#define KB    32     // k-chunk
#define NOUT  192    // 3*F stacked outputs
#define XROW  33     // padded x-tile row (conflict-free broadcast reads)
#define WROW  200    // padded weight-tile row (16B-aligned, conflict-free stores)

__global__ __launch_bounds__(256, 2)
void fused_gate_kernel(const float* __restrict__ x,
                       const float* __restrict__ Wt,
                       const float* __restrict__ bt,
                       const float* __restrict__ Wf,
                       const float* __restrict__ bf,
                       const float* __restrict__ Wg,
                       const float* __restrict__ bg,
                       const float* __restrict__ alpha,
                       float* __restrict__ out)
{
    // 48KB static smem, used as a union:
    //   main loop:  xs[TM][XROW] (2112 f) + ws[KB][WROW] (6400 f) = 8512 floats
    //   epilogue:   epi[TM][NOUT] = 12288 floats (49152 B)
    __shared__ float smem[12288];
    float* xs = smem;
    float* ws = smem + TM * XROW;

    const int tid  = threadIdx.x;
    const int r    = tid >> 4;      // 0..15 -> token group (4 tokens)
    const int c    = tid & 15;      // 0..15 -> output group (12 outputs)
    const int tok0 = blockIdx.x * TM;
    const int c12  = c * 12;
    const int t4   = r * 4;

    float acc[4][12];
    #pragma unroll
    for (int i = 0; i < 4; i++)
        #pragma unroll
        for (int j = 0; j < 12; j++) acc[i][j] = 0.f;

    for (int k0 = 0; k0 < DD; k0 += KB) {
        // ---- load x tile [TM][KB] (coalesced float4) ----
        #pragma unroll
        for (int p = tid; p < (TM * KB) / 4; p += 256) {
            int t  = p >> 3;            // KB/4 = 8 vec4 per token
            int kv = (p & 7) << 2;
            float4 v = *(const float4*)(x + (size_t)(tok0 + t) * DD + k0 + kv);
            float* dst = xs + t * XROW + kv;
            dst[0] = v.x; dst[1] = v.y; dst[2] = v.z; dst[3] = v.w;
        }
        // ---- W_top / W_feat tiles: [D,F] row-major, rows contiguous ----
        #pragma unroll
        for (int p = tid; p < (KB * FF) / 4; p += 256) {
            int kk = p >> 4;
            int fv = (p & 15) << 2;
            *(float4*)(ws + kk * WROW + fv)      = *(const float4*)(Wt + (size_t)(k0 + kk) * FF + fv);
            *(float4*)(ws + kk * WROW + FF + fv) = *(const float4*)(Wf + (size_t)(k0 + kk) * FF + fv);
        }
        // ---- W_gates [F,D]: transpose into ws[kk][128+f]; f-fast mapping
        //      gives conflict-free smem stores (f spans lanes) ----
        #pragma unroll
        for (int p = tid; p < (FF * KB) / 4; p += 256) {
            int f  = p & 63;
            int kv = (p >> 6) << 2;
            float4 g4 = *(const float4*)(Wg + (size_t)f * DD + k0 + kv);
            ws[(kv + 0) * WROW + 2 * FF + f] = g4.x;
            ws[(kv + 1) * WROW + 2 * FF + f] = g4.y;
            ws[(kv + 2) * WROW + 2 * FF + f] = g4.z;
            ws[(kv + 3) * WROW + 2 * FF + f] = g4.w;
        }
        __syncthreads();

        // ---- register-tiled FMA: 4 tokens x 12 outputs per thread ----
        #pragma unroll
        for (int kk = 0; kk < KB; ++kk) {
            float a0 = xs[(t4 + 0) * XROW + kk];
            float a1 = xs[(t4 + 1) * XROW + kk];
            float a2 = xs[(t4 + 2) * XROW + kk];
            float a3 = xs[(t4 + 3) * XROW + kk];
            const float* wrow = ws + kk * WROW + c12;
            float4 b0 = *(const float4*)(wrow);
            float4 b1 = *(const float4*)(wrow + 4);
            float4 b2 = *(const float4*)(wrow + 8);
            float bb[12] = {b0.x, b0.y, b0.z, b0.w,
                            b1.x, b1.y, b1.z, b1.w,
                            b2.x, b2.y, b2.z, b2.w};
            #pragma unroll
            for (int j = 0; j < 12; j++) {
                acc[0][j] = fmaf(a0, bb[j], acc[0][j]);
                acc[1][j] = fmaf(a1, bb[j], acc[1][j]);
                acc[2][j] = fmaf(a2, bb[j], acc[2][j]);
                acc[3][j] = fmaf(a3, bb[j], acc[3][j]);
            }
        }
        __syncthreads();
    }

    // ---- epilogue: transpose accumulators through smem ----
    float* epi = smem;
    #pragma unroll
    for (int i = 0; i < 4; i++)
        #pragma unroll
        for (int j = 0; j < 12; j++)
            epi[(t4 + i) * NOUT + c12 + j] = acc[i][j];
    __syncthreads();

    const float av = 1.f / (1.f + __expf(-alpha[0]));  // sigmoid(alpha)
    const int lane = tid & 31;
    const int wid  = tid >> 5;
    const unsigned FULLM = 0xffffffffu;
    const float NEGINF = __int_as_float(0xff800000);

    // one warp per token; each lane owns experts {lane, lane+32}
    for (int t = wid; t < TM; t += 8) {
        const float* row = epi + t * NOUT;
        float vt0 = row[lane]           + bt[lane];
        float vt1 = row[lane + 32]      + bt[lane + 32];
        float vf0 = row[FF + lane]      + bf[lane];
        float vf1 = row[FF + lane + 32] + bf[lane + 32];
        float g0  = 1.f / (1.f + __expf(-(row[2 * FF + lane]      + bg[lane])));
        float g1  = 1.f / (1.f + __expf(-(row[2 * FF + lane + 32] + bg[lane + 32])));

        // dense softmax branch: sum_f softmax(feat)_f * gate_f
        float m = fmaxf(vf0, vf1);
        #pragma unroll
        for (int o = 16; o; o >>= 1) m = fmaxf(m, __shfl_xor_sync(FULLM, m, o));
        float e0 = __expf(vf0 - m), e1 = __expf(vf1 - m);
        float fn = e0 * g0 + e1 * g1;
        float fd = e0 + e1;
        #pragma unroll
        for (int o = 16; o; o >>= 1) {
            fn += __shfl_xor_sync(FULLM, fn, o);
            fd += __shfl_xor_sync(FULLM, fd, o);
        }

        // top-8 branch: iterative warp-max selection (set-invariant vs top_k)
        bool r0 = false, r1 = false;
        float tn = 0.f, td = 0.f, vmax = 0.f;
        #pragma unroll
        for (int it = 0; it < TOPKK; ++it) {
            float c0 = r0 ? NEGINF : vt0;
            float c1 = r1 ? NEGINF : vt1;
            float cm = fmaxf(c0, c1);
            float m8 = cm;
            #pragma unroll
            for (int o = 16; o; o >>= 1) m8 = fmaxf(m8, __shfl_xor_sync(FULLM, m8, o));
            if (it == 0) vmax = m8;
            unsigned bal = __ballot_sync(FULLM, cm == m8);
            int owner = __ffs(bal) - 1;
            if (lane == owner) {
                if (!r0 && vt0 == m8) {
                    r0 = true;
                    float e = __expf(vt0 - vmax);
                    tn += e * g0; td += e;
                } else {
                    r1 = true;
                    float e = __expf(vt1 - vmax);
                    tn += e * g1; td += e;
                }
            }
        }
        #pragma unroll
        for (int o = 16; o; o >>= 1) {
            tn += __shfl_xor_sync(FULLM, tn, o);
            td += __shfl_xor_sync(FULLM, td, o);
        }

        if (lane == 0)
            out[tok0 + t] = av * (tn / td) + (1.f - av) * (fn / fd);
    }
}

extern "C" void kernel_launch(void* const* d_in, const int* in_sizes, int n_in,
                              void* d_out, int out_size) {
    const float* x  = (const float*)d_in[0];
    const float* Wt = (const float*)d_in[1];
    const float* bt = (const float*)d_in[2];
    const float* Wf = (const float*)d_in[3];
    const float* bf = (const float*)d_in[4];
    const float* Wg = (const float*)d_in[5];
    const float* bg = (const float*)d_in[6];
    const float* al = (const float*)d_in[7];
    float* out = (float*)d_out;
    const int ntok = out_size;  // B*S = 16384 (out is [B,S,1])
    fused_gate_kernel<<<ntok / TM, 256>>>(x, Wt, bt, Wf, bf, Wg, bg, al, out);
}

// round 5
// speedup vs baseline: 2.7905x; 2.7873x over previous
#include <cuda_runtime.h>
#include <cuda_bf16.h>
#include <cstdint>

#define NTOKENS 16384
#define DDIM    1024
#define FDIM    64
#define NOUTS   192
#define TILEK   64       // k per chunk
#define NCHUNK  16
#define MTOK    128      // tokens per CTA

// dynamic smem layout (bytes):
//  [0,768)        biases (192 f32)
//  [1024, +16K)   Xhi  (128 rows x 128B, SW128)
//  [+16K, +32K)   Xlo
//  [33792, ...)   W buffers: 2 x { Whi 24KB | Wlo 24KB }
#define XHI_OFF   1024
#define XLO_OFF   (1024 + 16384)
#define WBUF_OFF  33792
#define WLO_REL   24576
#define WBUF_STRIDE 49152
#define SMEM_BYTES  (WBUF_OFF + 2 * WBUF_STRIDE)   // 132096
#define EPI_OFF   1024
#define EPI_PITCH 193     // floats per token row (conflict-free)

__device__ __align__(16) __nv_bfloat16 g_Whi[NOUTS * DDIM];
__device__ __align__(16) __nv_bfloat16 g_Wlo[NOUTS * DDIM];

__device__ __forceinline__ uint32_t smem_u32(const void* p) {
    uint32_t a;
    asm("{ .reg .u64 t; cvta.to.shared.u64 t, %1; cvt.u32.u64 %0, t; }" : "=r"(a) : "l"(p));
    return a;
}
#define SW128(o) ((o) ^ (((o) >> 3) & 0x70))

#define CPASYNC16(dst, src) \
    asm volatile("cp.async.cg.shared.global [%0], [%1], 16;" :: "r"(dst), "l"(src) : "memory")
#define CP_COMMIT() asm volatile("cp.async.commit_group;" ::: "memory")
#define CP_WAIT0()  asm volatile("cp.async.wait_group 0;" ::: "memory")

#define LDSM4(r0, r1, r2, r3, addr) \
    asm volatile("ldmatrix.sync.aligned.m8n8.x4.shared.b16 {%0,%1,%2,%3}, [%4];" \
                 : "=r"(r0), "=r"(r1), "=r"(r2), "=r"(r3) : "r"(addr))

#define MMA_BF16(C, A, B) \
    asm volatile("mma.sync.aligned.m16n8k16.row.col.f32.bf16.bf16.f32 " \
                 "{%0,%1,%2,%3}, {%4,%5,%6,%7}, {%8,%9}, {%0,%1,%2,%3};" \
                 : "+f"((C)[0]), "+f"((C)[1]), "+f"((C)[2]), "+f"((C)[3]) \
                 : "r"((A)[0]), "r"((A)[1]), "r"((A)[2]), "r"((A)[3]), \
                   "r"((B)[0]), "r"((B)[1]))

#define STS128(addr, v) \
    asm volatile("st.shared.v4.b32 [%0], {%1,%2,%3,%4};" \
                 :: "r"(addr), "r"((v).x), "r"((v).y), "r"((v).z), "r"((v).w) : "memory")

// ---------- prep: split weights to bf16 hi/lo, combined [192 n][1024 k] ----------
__global__ void prep_w(const float* __restrict__ Wt, const float* __restrict__ Wf,
                       const float* __restrict__ Wg) {
    int idx = blockIdx.x * 256 + threadIdx.x;   // n = idx>>10, k = idx&1023
    int n = idx >> 10, k = idx & 1023;
    float v = (n < 64)  ? Wt[(size_t)k * FDIM + n]
            : (n < 128) ? Wf[(size_t)k * FDIM + (n - 64)]
                        : Wg[(size_t)(n - 128) * DDIM + k];
    __nv_bfloat16 h = __float2bfloat16(v);
    g_Whi[idx] = h;
    g_Wlo[idx] = __float2bfloat16(v - __bfloat162float(h));
}

// ---------- main ----------
__device__ __forceinline__ void ldg_x(const float* __restrict__ x, int tok0,
                                      int tid, int t, float4* xr) {
    #pragma unroll
    for (int j = 0; j < 4; j++) {
        int idx = tid + 256 * j;          // [0,1024)
        int row = idx >> 3, oc = idx & 7; // 8 x 8-float chunks per 64-float row
        const float4* p = reinterpret_cast<const float4*>(
            x + (size_t)(tok0 + row) * DDIM + t * TILEK + oc * 8);
        xr[2 * j]     = p[0];
        xr[2 * j + 1] = p[1];
    }
}

__device__ __forceinline__ void cp_w_chunk(uint32_t wdst, int t, int tid) {
    const char* hb = reinterpret_cast<const char*>(g_Whi);
    const char* lb = reinterpret_cast<const char*>(g_Wlo);
    #pragma unroll
    for (int j = 0; j < 6; j++) {
        int idx = tid + 256 * j;          // [0,1536)
        int nrow = idx >> 3, c = idx & 7;
        size_t go = (size_t)nrow * 2048 + (size_t)t * 128 + c * 16;
        uint32_t off = SW128((uint32_t)(nrow * 128 + c * 16));
        CPASYNC16(wdst + off,           hb + go);
        CPASYNC16(wdst + WLO_REL + off, lb + go);
    }
}

__global__ __launch_bounds__(256, 1)
void moe_gate_main(const float* __restrict__ x,
                   const float* __restrict__ bt, const float* __restrict__ bfe,
                   const float* __restrict__ bg, const float* __restrict__ alpha,
                   float* __restrict__ out) {
    extern __shared__ char smem[];
    const uint32_t sb = smem_u32(smem);
    const int tid  = threadIdx.x;
    const int wid  = tid >> 5;
    const int lane = tid & 31;
    const int tok0 = blockIdx.x * MTOK;

    float* biass = reinterpret_cast<float*>(smem);
    if (tid < 192)
        biass[tid] = (tid < 64) ? bt[tid] : (tid < 128) ? bfe[tid - 64] : bg[tid - 128];

    // warp tile: 2 (M) x 4 (N)
    const int WT    = (wid & 1) * 64;      // warp token base
    const int nbase = (wid >> 1) * 48;     // warp out-col base

    // ldmatrix lane-address components (constant per thread)
    const uint32_t aRow = ((lane >> 3) & 1) * 8 + (lane & 7);   // A: +8 row for m1,m3
    const uint32_t aK   = ((lane >> 4) & 1) * 16;               // A: +16B k for m2,m3
    const uint32_t bRow = ((lane >> 4) & 1) * 8 + (lane & 7);   // B: +8 n for m2,m3
    const uint32_t bK   = ((lane >> 3) & 1) * 16;               // B: +16B k for m1,m3

    float acc[4][6][4];
    #pragma unroll
    for (int i = 0; i < 4; i++)
        #pragma unroll
        for (int j = 0; j < 6; j++)
            #pragma unroll
            for (int c = 0; c < 4; c++) acc[i][j][c] = 0.f;

    float4 xr[8];
    ldg_x(x, tok0, tid, 0, xr);
    cp_w_chunk(sb + WBUF_OFF, 0, tid);
    CP_COMMIT();

    for (int t = 0; t < NCHUNK; ++t) {
        const uint32_t wbase = sb + WBUF_OFF + (t & 1) * WBUF_STRIDE;

        CP_WAIT0();   // W(t) resident

        // x(t): fp32 regs -> hi/lo bf16 smem (SW128)
        #pragma unroll
        for (int j = 0; j < 4; j++) {
            int idx = tid + 256 * j;
            int row = idx >> 3, oc = idx & 7;
            const float* fp = reinterpret_cast<const float*>(&xr[2 * j]);
            uint4 hv, lv;
            uint32_t* hw = reinterpret_cast<uint32_t*>(&hv);
            uint32_t* lw = reinterpret_cast<uint32_t*>(&lv);
            #pragma unroll
            for (int e = 0; e < 4; e++) {
                float a = fp[2 * e], b = fp[2 * e + 1];
                __nv_bfloat16 ah = __float2bfloat16(a), bh = __float2bfloat16(b);
                float al = a - __bfloat162float(ah);
                float bl = b - __bfloat162float(bh);
                __nv_bfloat162 hp = __halves2bfloat162(ah, bh);
                __nv_bfloat162 lp = __floats2bfloat162_rn(al, bl);
                hw[e] = *reinterpret_cast<uint32_t*>(&hp);
                lw[e] = *reinterpret_cast<uint32_t*>(&lp);
            }
            uint32_t off = SW128((uint32_t)(row * 128 + oc * 16));
            STS128(sb + XHI_OFF + off, hv);
            STS128(sb + XLO_OFF + off, lv);
        }
        __syncthreads();

        if (t + 1 < NCHUNK) {
            cp_w_chunk(sb + WBUF_OFF + ((t + 1) & 1) * WBUF_STRIDE, t + 1, tid);
            CP_COMMIT();
            ldg_x(x, tok0, tid, t + 1, xr);
        }

        // compute: 4 k-steps of 16
        #pragma unroll
        for (int ks = 0; ks < 4; ++ks) {
            uint32_t Ahi[4][4], Alo[4][4], Bhi[6][2], Blo[6][2];
            #pragma unroll
            for (int mt = 0; mt < 4; mt++) {
                uint32_t off = SW128((uint32_t)((WT + mt * 16 + aRow) * 128 + ks * 32 + aK));
                LDSM4(Ahi[mt][0], Ahi[mt][1], Ahi[mt][2], Ahi[mt][3], sb + XHI_OFF + off);
                LDSM4(Alo[mt][0], Alo[mt][1], Alo[mt][2], Alo[mt][3], sb + XLO_OFF + off);
            }
            #pragma unroll
            for (int bp = 0; bp < 3; bp++) {   // each x4 covers 2 n-tiles
                uint32_t off = SW128((uint32_t)((nbase + bp * 16 + bRow) * 128 + ks * 32 + bK));
                LDSM4(Bhi[2 * bp][0], Bhi[2 * bp][1], Bhi[2 * bp + 1][0], Bhi[2 * bp + 1][1],
                      wbase + off);
                LDSM4(Blo[2 * bp][0], Blo[2 * bp][1], Blo[2 * bp + 1][0], Blo[2 * bp + 1][1],
                      wbase + WLO_REL + off);
            }
            #pragma unroll
            for (int mt = 0; mt < 4; mt++)
                #pragma unroll
                for (int nt = 0; nt < 6; nt++) {
                    MMA_BF16(acc[mt][nt], Ahi[mt], Bhi[nt]);
                    MMA_BF16(acc[mt][nt], Alo[mt], Bhi[nt]);
                    MMA_BF16(acc[mt][nt], Ahi[mt], Blo[nt]);
                }
        }
        __syncthreads();
    }

    // ---------------- epilogue ----------------
    float* epi = reinterpret_cast<float*>(smem + EPI_OFF);
    const int rg = lane >> 2;          // group row 0..7
    const int cp2 = (lane & 3) * 2;    // col pair
    #pragma unroll
    for (int mt = 0; mt < 4; mt++)
        #pragma unroll
        for (int nt = 0; nt < 6; nt++) {
            int r0 = WT + mt * 16 + rg;
            int c0 = nbase + nt * 8 + cp2;
            epi[r0 * EPI_PITCH + c0]           = acc[mt][nt][0];
            epi[r0 * EPI_PITCH + c0 + 1]       = acc[mt][nt][1];
            epi[(r0 + 8) * EPI_PITCH + c0]     = acc[mt][nt][2];
            epi[(r0 + 8) * EPI_PITCH + c0 + 1] = acc[mt][nt][3];
        }
    __syncthreads();

    if (tid < MTOK) {
        const float* row = epi + tid * EPI_PITCH;
        const float asig = 1.f / (1.f + __expf(-alpha[0]));
        float v[64], g[64];

        #pragma unroll
        for (int i = 0; i < 64; i++)
            g[i] = 1.f / (1.f + __expf(-(row[128 + i] + biass[128 + i])));
        #pragma unroll
        for (int i = 0; i < 64; i++) v[i] = row[i] + biass[i];

        // top-8 by iterative threshold
        float m0 = v[0];
        #pragma unroll
        for (int i = 1; i < 64; i++) m0 = fmaxf(m0, v[i]);
        float prev = m0;
        for (int it = 0; it < 7; ++it) {
            float m = -3.4e38f;
            #pragma unroll
            for (int i = 0; i < 64; i++) {
                float c = (v[i] < prev) ? v[i] : -3.4e38f;
                m = fmaxf(m, c);
            }
            prev = m;
        }
        float tn = 0.f, td = 0.f;
        #pragma unroll
        for (int i = 0; i < 64; i++) {
            if (v[i] >= prev) {
                float e = __expf(v[i] - m0);
                tn += e * g[i]; td += e;
            }
        }

        // dense softmax branch
        #pragma unroll
        for (int i = 0; i < 64; i++) v[i] = row[64 + i] + biass[64 + i];
        float mf = v[0];
        #pragma unroll
        for (int i = 1; i < 64; i++) mf = fmaxf(mf, v[i]);
        float fn = 0.f, fd = 0.f;
        #pragma unroll
        for (int i = 0; i < 64; i++) {
            float e = __expf(v[i] - mf);
            fn += e * g[i]; fd += e;
        }

        out[tok0 + tid] = asig * (tn / td) + (1.f - asig) * (fn / fd);
    }
}

extern "C" void kernel_launch(void* const* d_in, const int* in_sizes, int n_in,
                              void* d_out, int out_size) {
    const float* x  = (const float*)d_in[0];
    const float* Wt = (const float*)d_in[1];
    const float* bt = (const float*)d_in[2];
    const float* Wf = (const float*)d_in[3];
    const float* bf = (const float*)d_in[4];
    const float* Wg = (const float*)d_in[5];
    const float* bg = (const float*)d_in[6];
    const float* al = (const float*)d_in[7];
    float* out = (float*)d_out;

    cudaFuncSetAttribute(moe_gate_main,
                         cudaFuncAttributeMaxDynamicSharedMemorySize, SMEM_BYTES);
    prep_w<<<NOUTS * DDIM / 256, 256>>>(Wt, Wf, Wg);
    moe_gate_main<<<NTOKENS / MTOK, 256, SMEM_BYTES>>>(x, bt, bf, bg, al, out);
}

// round 7
// speedup vs baseline: 2.9090x; 1.0425x over previous
#include <cuda_runtime.h>
#include <cuda_bf16.h>
#include <cstdint>

#define NTOKENS 16384
#define DDIM    1024
#define FDIM    64
#define NOUTS   192
#define TILEK   64
#define NCHUNK  16
#define MTOK    128

// smem (bytes):
//  [0,768)    biases
//  [768,800)  mbarriers: full0@768 full1@776 empty0@784 empty1@792
//  X stages:  X0@1024, X1@33792   (each: hi 16K | lo 16K)
//  W stages:  W0@66560, W1@115712 (each: hi 24K | lo 24K)
#define BAR_FULL0 768
#define BAR_FULL1 776
#define BAR_EMPTY0 784
#define BAR_EMPTY1 792
#define XOFF      1024
#define XSTRIDE   32768
#define XLO_REL   16384
#define WOFF      66560
#define WSTRIDE   49152
#define WLO_REL   24576
#define SMEM_BYTES (WOFF + 2 * WSTRIDE)   // 164864
#define EPI_OFF   1024
#define EPI_PITCH 193

__device__ __align__(16) __nv_bfloat16 g_Whi[NOUTS * DDIM];
__device__ __align__(16) __nv_bfloat16 g_Wlo[NOUTS * DDIM];

__device__ __forceinline__ uint32_t smem_u32(const void* p) {
    uint32_t a;
    asm("{ .reg .u64 t; cvta.to.shared.u64 t, %1; cvt.u32.u64 %0, t; }" : "=r"(a) : "l"(p));
    return a;
}
#define SW128(o) ((o) ^ (((o) >> 3) & 0x70))

#define CPASYNC16(dst, src) \
    asm volatile("cp.async.cg.shared.global [%0], [%1], 16;" :: "r"(dst), "l"(src) : "memory")
#define CP_COMMIT() asm volatile("cp.async.commit_group;" ::: "memory")
#define CP_WAIT0()  asm volatile("cp.async.wait_group 0;" ::: "memory")

#define MBAR_INIT(addr, cnt) \
    asm volatile("mbarrier.init.shared.b64 [%0], %1;" :: "r"(addr), "r"((uint32_t)(cnt)) : "memory")
#define MBAR_ARRIVE(addr) \
    asm volatile("mbarrier.arrive.shared.b64 _, [%0];" :: "r"(addr) : "memory")
#define MBAR_WAIT(mbar, par) do { \
    uint32_t _m = (uint32_t)(mbar), _p = (uint32_t)(par), _d; \
    asm volatile("{\n\t.reg .pred p;\n\t" \
        "mbarrier.try_wait.parity.acquire.cta.shared::cta.b64 p, [%1], %2;\n\t" \
        "selp.b32 %0, 1, 0, p;\n\t}" : "=r"(_d) : "r"(_m), "r"(_p) : "memory"); \
    if (!_d) { \
        asm volatile("{\n\t.reg .pred P1;\n\t" \
            "WL_%=:\n\t" \
            "mbarrier.try_wait.parity.acquire.cta.shared::cta.b64 P1, [%0], %1, 0x989680;\n\t" \
            "@P1 bra.uni WD_%=;\n\t" \
            "bra.uni WL_%=;\n\t" \
            "WD_%=:\n\t}" :: "r"(_m), "r"(_p) : "memory"); \
    } \
} while (0)

#define LDSM4(r0, r1, r2, r3, addr) \
    asm volatile("ldmatrix.sync.aligned.m8n8.x4.shared.b16 {%0,%1,%2,%3}, [%4];" \
                 : "=r"(r0), "=r"(r1), "=r"(r2), "=r"(r3) : "r"(addr))

#define MMA_BF16(C, A, B) \
    asm volatile("mma.sync.aligned.m16n8k16.row.col.f32.bf16.bf16.f32 " \
                 "{%0,%1,%2,%3}, {%4,%5,%6,%7}, {%8,%9}, {%0,%1,%2,%3};" \
                 : "+f"((C)[0]), "+f"((C)[1]), "+f"((C)[2]), "+f"((C)[3]) \
                 : "r"((A)[0]), "r"((A)[1]), "r"((A)[2]), "r"((A)[3]), \
                   "r"((B)[0]), "r"((B)[1]))

#define STS128(addr, v) \
    asm volatile("st.shared.v4.b32 [%0], {%1,%2,%3,%4};" \
                 :: "r"(addr), "r"((v).x), "r"((v).y), "r"((v).z), "r"((v).w) : "memory")

// ---------- prep: split weights to bf16 hi/lo, combined [192 n][1024 k] ----------
__global__ void prep_w(const float* __restrict__ Wt, const float* __restrict__ Wf,
                       const float* __restrict__ Wg) {
    int idx = blockIdx.x * 256 + threadIdx.x;
    int n = idx >> 10, k = idx & 1023;
    float v = (n < 64)  ? Wt[(size_t)k * FDIM + n]
            : (n < 128) ? Wf[(size_t)k * FDIM + (n - 64)]
                        : Wg[(size_t)(n - 128) * DDIM + k];
    __nv_bfloat16 h = __float2bfloat16(v);
    g_Whi[idx] = h;
    g_Wlo[idx] = __float2bfloat16(v - __bfloat162float(h));
}

// ---------- main: 8 consumer warps (MMA) + 2 producer warps (X/W feed) ----------
__global__ __launch_bounds__(320, 1)
void moe_gate_main(const float* __restrict__ x,
                   const float* __restrict__ bt, const float* __restrict__ bfe,
                   const float* __restrict__ bg, const float* __restrict__ alpha,
                   float* __restrict__ out) {
    extern __shared__ char smem[];
    const uint32_t sb = smem_u32(smem);
    const int tid  = threadIdx.x;
    const int wid  = tid >> 5;
    const int lane = tid & 31;
    const int tok0 = blockIdx.x * MTOK;

    float* biass = reinterpret_cast<float*>(smem);
    if (tid < 192)
        biass[tid] = (tid < 64) ? bt[tid] : (tid < 128) ? bfe[tid - 64] : bg[tid - 128];
    if (tid == 0) {
        MBAR_INIT(sb + BAR_FULL0, 64);
        MBAR_INIT(sb + BAR_FULL1, 64);
        MBAR_INIT(sb + BAR_EMPTY0, 256);
        MBAR_INIT(sb + BAR_EMPTY1, 256);
    }
    __syncthreads();

    float acc[4][6][4];

    if (wid < 8) {
        // ================= consumers =================
        const int WT    = (wid & 1) * 64;
        const int nbase = (wid >> 1) * 48;
        const uint32_t aRow = ((lane >> 3) & 1) * 8 + (lane & 7);
        const uint32_t aK   = ((lane >> 4) & 1) * 16;
        const uint32_t bRow = ((lane >> 4) & 1) * 8 + (lane & 7);
        const uint32_t bK   = ((lane >> 3) & 1) * 16;

        #pragma unroll
        for (int i = 0; i < 4; i++)
            #pragma unroll
            for (int j = 0; j < 6; j++)
                #pragma unroll
                for (int c = 0; c < 4; c++) acc[i][j][c] = 0.f;

        for (int t = 0; t < NCHUNK; ++t) {
            const int s = t & 1;
            MBAR_WAIT(sb + (s ? BAR_FULL1 : BAR_FULL0), (t >> 1) & 1);

            const uint32_t xhi = sb + XOFF + s * XSTRIDE;
            const uint32_t xlo = xhi + XLO_REL;
            const uint32_t whi = sb + WOFF + s * WSTRIDE;
            const uint32_t wlo = whi + WLO_REL;

            #pragma unroll
            for (int ks = 0; ks < 4; ++ks) {
                uint32_t Ahi[4][4], Alo[4][4], Bhi[6][2], Blo[6][2];
                #pragma unroll
                for (int mt = 0; mt < 4; mt++) {
                    uint32_t off = SW128((uint32_t)((WT + mt * 16 + aRow) * 128 + ks * 32 + aK));
                    LDSM4(Ahi[mt][0], Ahi[mt][1], Ahi[mt][2], Ahi[mt][3], xhi + off);
                    LDSM4(Alo[mt][0], Alo[mt][1], Alo[mt][2], Alo[mt][3], xlo + off);
                }
                #pragma unroll
                for (int bp = 0; bp < 3; bp++) {
                    uint32_t off = SW128((uint32_t)((nbase + bp * 16 + bRow) * 128 + ks * 32 + bK));
                    LDSM4(Bhi[2 * bp][0], Bhi[2 * bp][1], Bhi[2 * bp + 1][0], Bhi[2 * bp + 1][1],
                          whi + off);
                    LDSM4(Blo[2 * bp][0], Blo[2 * bp][1], Blo[2 * bp + 1][0], Blo[2 * bp + 1][1],
                          wlo + off);
                }
                #pragma unroll
                for (int mt = 0; mt < 4; mt++)
                    #pragma unroll
                    for (int nt = 0; nt < 6; nt++) {
                        MMA_BF16(acc[mt][nt], Ahi[mt], Bhi[nt]);
                        MMA_BF16(acc[mt][nt], Alo[mt], Bhi[nt]);
                        MMA_BF16(acc[mt][nt], Ahi[mt], Blo[nt]);
                    }
            }
            MBAR_ARRIVE(sb + (s ? BAR_EMPTY1 : BAR_EMPTY0));
        }
    } else {
        // ================= producers (2 warps, 64 threads) =================
        const int ptid = tid - 256;
        const char* hb = reinterpret_cast<const char*>(g_Whi);
        const char* lb = reinterpret_cast<const char*>(g_Wlo);

        for (int t = 0; t < NCHUNK; ++t) {
            const int s = t & 1;
            if (t >= 2) MBAR_WAIT(sb + (s ? BAR_EMPTY1 : BAR_EMPTY0), ((t - 2) >> 1) & 1);

            // W chunk via cp.async (issued first, overlaps x convert below)
            const uint32_t wdst = sb + WOFF + s * WSTRIDE;
            #pragma unroll
            for (int j = 0; j < 24; j++) {
                int idx = ptid + 64 * j;                 // [0,1536)
                int nrow = idx >> 3, c = idx & 7;
                size_t go = (size_t)nrow * 2048 + (size_t)t * 128 + c * 16;
                uint32_t off = SW128((uint32_t)(nrow * 128 + c * 16));
                CPASYNC16(wdst + off,           hb + go);
                CPASYNC16(wdst + WLO_REL + off, lb + go);
            }
            CP_COMMIT();

            // x chunk: ldg -> hi/lo bf16 -> smem (SW128)
            const uint32_t xb = sb + XOFF + s * XSTRIDE;
            #pragma unroll
            for (int j = 0; j < 16; j++) {
                int q = ptid + 64 * j;                   // [0,1024) groups of 8 floats
                int row = q >> 3, oc = q & 7;
                const float4* p = reinterpret_cast<const float4*>(
                    x + (size_t)(tok0 + row) * DDIM + t * TILEK + oc * 8);
                float4 f0 = p[0], f1 = p[1];
                const float fp[8] = {f0.x, f0.y, f0.z, f0.w, f1.x, f1.y, f1.z, f1.w};
                uint4 hv, lv;
                uint32_t* hw = reinterpret_cast<uint32_t*>(&hv);
                uint32_t* lw = reinterpret_cast<uint32_t*>(&lv);
                #pragma unroll
                for (int e = 0; e < 4; e++) {
                    float a = fp[2 * e], b = fp[2 * e + 1];
                    __nv_bfloat16 ah = __float2bfloat16(a), bh = __float2bfloat16(b);
                    float al = a - __bfloat162float(ah);
                    float bl = b - __bfloat162float(bh);
                    __nv_bfloat162 hp = __halves2bfloat162(ah, bh);
                    __nv_bfloat162 lp = __floats2bfloat162_rn(al, bl);
                    hw[e] = *reinterpret_cast<uint32_t*>(&hp);
                    lw[e] = *reinterpret_cast<uint32_t*>(&lp);
                }
                uint32_t off = SW128((uint32_t)(row * 128 + oc * 16));
                STS128(xb + off,           hv);
                STS128(xb + XLO_REL + off, lv);
            }
            CP_WAIT0();   // this thread's cp.asyncs landed
            MBAR_ARRIVE(sb + (s ? BAR_FULL1 : BAR_FULL0));
        }
    }

    __syncthreads();   // pipeline done; smem free for epilogue

    // ---------------- epilogue ----------------
    float* epi = reinterpret_cast<float*>(smem + EPI_OFF);
    if (wid < 8) {
        const int WT    = (wid & 1) * 64;
        const int nbase = (wid >> 1) * 48;
        const int rg  = lane >> 2;
        const int cp2 = (lane & 3) * 2;
        #pragma unroll
        for (int mt = 0; mt < 4; mt++)
            #pragma unroll
            for (int nt = 0; nt < 6; nt++) {
                int r0 = WT + mt * 16 + rg;
                int c0 = nbase + nt * 8 + cp2;
                epi[r0 * EPI_PITCH + c0]           = acc[mt][nt][0];
                epi[r0 * EPI_PITCH + c0 + 1]       = acc[mt][nt][1];
                epi[(r0 + 8) * EPI_PITCH + c0]     = acc[mt][nt][2];
                epi[(r0 + 8) * EPI_PITCH + c0 + 1] = acc[mt][nt][3];
            }
    }
    __syncthreads();

    if (tid < MTOK) {
        const float* row = epi + tid * EPI_PITCH;
        const float asig = 1.f / (1.f + __expf(-alpha[0]));
        float v[64], g[64];

        #pragma unroll
        for (int i = 0; i < 64; i++)
            g[i] = 1.f / (1.f + __expf(-(row[128 + i] + biass[128 + i])));
        #pragma unroll
        for (int i = 0; i < 64; i++) v[i] = row[i] + biass[i];

        float m0 = v[0];
        #pragma unroll
        for (int i = 1; i < 64; i++) m0 = fmaxf(m0, v[i]);
        float prev = m0;
        for (int it = 0; it < 7; ++it) {
            float m = -3.4e38f;
            #pragma unroll
            for (int i = 0; i < 64; i++) {
                float c = (v[i] < prev) ? v[i] : -3.4e38f;
                m = fmaxf(m, c);
            }
            prev = m;
        }
        float tn = 0.f, td = 0.f;
        #pragma unroll
        for (int i = 0; i < 64; i++) {
            if (v[i] >= prev) {
                float e = __expf(v[i] - m0);
                tn += e * g[i]; td += e;
            }
        }

        #pragma unroll
        for (int i = 0; i < 64; i++) v[i] = row[64 + i] + biass[64 + i];
        float mf = v[0];
        #pragma unroll
        for (int i = 1; i < 64; i++) mf = fmaxf(mf, v[i]);
        float fn = 0.f, fd = 0.f;
        #pragma unroll
        for (int i = 0; i < 64; i++) {
            float e = __expf(v[i] - mf);
            fn += e * g[i]; fd += e;
        }

        out[tok0 + tid] = asig * (tn / td) + (1.f - asig) * (fn / fd);
    }
}

extern "C" void kernel_launch(void* const* d_in, const int* in_sizes, int n_in,
                              void* d_out, int out_size) {
    const float* x  = (const float*)d_in[0];
    const float* Wt = (const float*)d_in[1];
    const float* bt = (const float*)d_in[2];
    const float* Wf = (const float*)d_in[3];
    const float* bf = (const float*)d_in[4];
    const float* Wg = (const float*)d_in[5];
    const float* bg = (const float*)d_in[6];
    const float* al = (const float*)d_in[7];
    float* out = (float*)d_out;

    cudaFuncSetAttribute(moe_gate_main,
                         cudaFuncAttributeMaxDynamicSharedMemorySize, SMEM_BYTES);
    prep_w<<<NOUTS * DDIM / 256, 256>>>(Wt, Wf, Wg);
    moe_gate_main<<<NTOKENS / MTOK, 320, SMEM_BYTES>>>(x, bt, bf, bg, al, out);
}

// round 9
// speedup vs baseline: 2.9893x; 1.0276x over previous
#include <cuda_runtime.h>
#include <cuda_bf16.h>
#include <cstdint>

#define NTOKENS 16384
#define DDIM    1024
#define FDIM    64
#define NOUTS   192
#define TILEK   64
#define NCHUNK  16
#define MTOK    128

// smem (bytes):
//  [0,768)    biases
//  [768,800)  mbarriers: full0@768 full1@776 empty0@784 empty1@792
//  X stages:  X0@1024, X1@33792   (each: hi 16K | lo 16K)
//  W stages:  W0@66560, W1@115712 (each: hi 24K | lo 24K)
#define BAR_FULL0 768
#define BAR_FULL1 776
#define BAR_EMPTY0 784
#define BAR_EMPTY1 792
#define XOFF      1024
#define XSTRIDE   32768
#define XLO_REL   16384
#define WOFF      66560
#define WSTRIDE   49152
#define WLO_REL   24576
#define SMEM_BYTES (WOFF + 2 * WSTRIDE)   // 164864
#define EPI_OFF   1024
#define EPI_PITCH 193

__device__ __align__(16) __nv_bfloat16 g_Whi[NOUTS * DDIM];
__device__ __align__(16) __nv_bfloat16 g_Wlo[NOUTS * DDIM];

__device__ __forceinline__ uint32_t smem_u32(const void* p) {
    uint32_t a;
    asm("{ .reg .u64 t; cvta.to.shared.u64 t, %1; cvt.u32.u64 %0, t; }" : "=r"(a) : "l"(p));
    return a;
}
#define SW128(o) ((o) ^ (((o) >> 3) & 0x70))

#define CPASYNC16(dst, src) \
    asm volatile("cp.async.cg.shared.global [%0], [%1], 16;" :: "r"(dst), "l"(src) : "memory")
#define CP_COMMIT() asm volatile("cp.async.commit_group;" ::: "memory")
#define CP_WAIT0()  asm volatile("cp.async.wait_group 0;" ::: "memory")

#define MBAR_INIT(addr, cnt) \
    asm volatile("mbarrier.init.shared.b64 [%0], %1;" :: "r"(addr), "r"((uint32_t)(cnt)) : "memory")
#define MBAR_ARRIVE(addr) \
    asm volatile("mbarrier.arrive.shared.b64 _, [%0];" :: "r"(addr) : "memory")
#define MBAR_WAIT(mbar, par) do { \
    uint32_t _m = (uint32_t)(mbar), _p = (uint32_t)(par), _d; \
    asm volatile("{\n\t.reg .pred p;\n\t" \
        "mbarrier.try_wait.parity.acquire.cta.shared::cta.b64 p, [%1], %2;\n\t" \
        "selp.b32 %0, 1, 0, p;\n\t}" : "=r"(_d) : "r"(_m), "r"(_p) : "memory"); \
    if (!_d) { \
        asm volatile("{\n\t.reg .pred P1;\n\t" \
            "WL_%=:\n\t" \
            "mbarrier.try_wait.parity.acquire.cta.shared::cta.b64 P1, [%0], %1, 0x989680;\n\t" \
            "@P1 bra.uni WD_%=;\n\t" \
            "bra.uni WL_%=;\n\t" \
            "WD_%=:\n\t}" :: "r"(_m), "r"(_p) : "memory"); \
    } \
} while (0)

#define LDSM4(r0, r1, r2, r3, addr) \
    asm volatile("ldmatrix.sync.aligned.m8n8.x4.shared.b16 {%0,%1,%2,%3}, [%4];" \
                 : "=r"(r0), "=r"(r1), "=r"(r2), "=r"(r3) : "r"(addr))

#define MMA_BF16(C, A, B) \
    asm volatile("mma.sync.aligned.m16n8k16.row.col.f32.bf16.bf16.f32 " \
                 "{%0,%1,%2,%3}, {%4,%5,%6,%7}, {%8,%9}, {%0,%1,%2,%3};" \
                 : "+f"((C)[0]), "+f"((C)[1]), "+f"((C)[2]), "+f"((C)[3]) \
                 : "r"((A)[0]), "r"((A)[1]), "r"((A)[2]), "r"((A)[3]), \
                   "r"((B)[0]), "r"((B)[1]))

#define STS128(addr, v) \
    asm volatile("st.shared.v4.b32 [%0], {%1,%2,%3,%4};" \
                 :: "r"(addr), "r"((v).x), "r"((v).y), "r"((v).z), "r"((v).w) : "memory")

// ---------- prep: split weights to bf16 hi/lo, combined [192 n][1024 k] ----------
__global__ void prep_w(const float* __restrict__ Wt, const float* __restrict__ Wf,
                       const float* __restrict__ Wg) {
    int idx = blockIdx.x * 256 + threadIdx.x;
    int n = idx >> 10, k = idx & 1023;
    float v = (n < 64)  ? Wt[(size_t)k * FDIM + n]
            : (n < 128) ? Wf[(size_t)k * FDIM + (n - 64)]
                        : Wg[(size_t)(n - 128) * DDIM + k];
    __nv_bfloat16 h = __float2bfloat16(v);
    g_Whi[idx] = h;
    g_Wlo[idx] = __float2bfloat16(v - __bfloat162float(h));
}

// ---------- main: 8 consumer warps (MMA) + 2 producer warps (X/W feed) ----------
__global__ __launch_bounds__(320, 1)
void moe_gate_main(const float* __restrict__ x,
                   const float* __restrict__ bt, const float* __restrict__ bfe,
                   const float* __restrict__ bg, const float* __restrict__ alpha,
                   float* __restrict__ out) {
    extern __shared__ char smem[];
    const uint32_t sb = smem_u32(smem);
    const int tid  = threadIdx.x;
    const int wid  = tid >> 5;
    const int lane = tid & 31;
    const int tok0 = blockIdx.x * MTOK;

    float* biass = reinterpret_cast<float*>(smem);
    if (tid < 192)
        biass[tid] = (tid < 64) ? bt[tid] : (tid < 128) ? bfe[tid - 64] : bg[tid - 128];
    if (tid == 0) {
        MBAR_INIT(sb + BAR_FULL0, 64);
        MBAR_INIT(sb + BAR_FULL1, 64);
        MBAR_INIT(sb + BAR_EMPTY0, 256);
        MBAR_INIT(sb + BAR_EMPTY1, 256);
    }
    __syncthreads();

    float acc[4][6][4];

    if (wid < 8) {
        // ================= consumers =================
        const int WT    = (wid & 1) * 64;
        const int nbase = (wid >> 1) * 48;
        const uint32_t aRow = ((lane >> 3) & 1) * 8 + (lane & 7);
        const uint32_t aK   = ((lane >> 4) & 1) * 16;
        const uint32_t bRow = ((lane >> 4) & 1) * 8 + (lane & 7);
        const uint32_t bK   = ((lane >> 3) & 1) * 16;

        #pragma unroll
        for (int i = 0; i < 4; i++)
            #pragma unroll
            for (int j = 0; j < 6; j++)
                #pragma unroll
                for (int c = 0; c < 4; c++) acc[i][j][c] = 0.f;

        for (int t = 0; t < NCHUNK; ++t) {
            const int s = t & 1;
            MBAR_WAIT(sb + (s ? BAR_FULL1 : BAR_FULL0), (t >> 1) & 1);

            const uint32_t xhi = sb + XOFF + s * XSTRIDE;
            const uint32_t xlo = xhi + XLO_REL;
            const uint32_t whi = sb + WOFF + s * WSTRIDE;
            const uint32_t wlo = whi + WLO_REL;

            #pragma unroll
            for (int ks = 0; ks < 4; ++ks) {
                uint32_t Ahi[4][4], Alo[4][4], Bhi[6][2], Blo[6][2];
                #pragma unroll
                for (int mt = 0; mt < 4; mt++) {
                    uint32_t off = SW128((uint32_t)((WT + mt * 16 + aRow) * 128 + ks * 32 + aK));
                    LDSM4(Ahi[mt][0], Ahi[mt][1], Ahi[mt][2], Ahi[mt][3], xhi + off);
                    LDSM4(Alo[mt][0], Alo[mt][1], Alo[mt][2], Alo[mt][3], xlo + off);
                }
                #pragma unroll
                for (int bp = 0; bp < 3; bp++) {
                    uint32_t off = SW128((uint32_t)((nbase + bp * 16 + bRow) * 128 + ks * 32 + bK));
                    LDSM4(Bhi[2 * bp][0], Bhi[2 * bp][1], Bhi[2 * bp + 1][0], Bhi[2 * bp + 1][1],
                          whi + off);
                    LDSM4(Blo[2 * bp][0], Blo[2 * bp][1], Blo[2 * bp + 1][0], Blo[2 * bp + 1][1],
                          wlo + off);
                }
                // pass-outermost: same-acc reuse distance = 24 MMAs (covers HMMA latency)
                #pragma unroll
                for (int mt = 0; mt < 4; mt++)
                    #pragma unroll
                    for (int nt = 0; nt < 6; nt++)
                        MMA_BF16(acc[mt][nt], Ahi[mt], Bhi[nt]);
                #pragma unroll
                for (int mt = 0; mt < 4; mt++)
                    #pragma unroll
                    for (int nt = 0; nt < 6; nt++)
                        MMA_BF16(acc[mt][nt], Alo[mt], Bhi[nt]);
                #pragma unroll
                for (int mt = 0; mt < 4; mt++)
                    #pragma unroll
                    for (int nt = 0; nt < 6; nt++)
                        MMA_BF16(acc[mt][nt], Ahi[mt], Blo[nt]);
            }
            MBAR_ARRIVE(sb + (s ? BAR_EMPTY1 : BAR_EMPTY0));
        }
    } else {
        // ================= producers (2 warps, 64 threads) =================
        const int ptid = tid - 256;
        const char* hb = reinterpret_cast<const char*>(g_Whi);
        const char* lb = reinterpret_cast<const char*>(g_Wlo);

        for (int t = 0; t < NCHUNK; ++t) {
            const int s = t & 1;
            if (t >= 2) MBAR_WAIT(sb + (s ? BAR_EMPTY1 : BAR_EMPTY0), ((t - 2) >> 1) & 1);

            const uint32_t wdst = sb + WOFF + s * WSTRIDE;
            #pragma unroll
            for (int j = 0; j < 24; j++) {
                int idx = ptid + 64 * j;                 // [0,1536)
                int nrow = idx >> 3, c = idx & 7;
                size_t go = (size_t)nrow * 2048 + (size_t)t * 128 + c * 16;
                uint32_t off = SW128((uint32_t)(nrow * 128 + c * 16));
                CPASYNC16(wdst + off,           hb + go);
                CPASYNC16(wdst + WLO_REL + off, lb + go);
            }
            CP_COMMIT();

            const uint32_t xb = sb + XOFF + s * XSTRIDE;
            #pragma unroll
            for (int j = 0; j < 16; j++) {
                int q = ptid + 64 * j;                   // [0,1024) groups of 8 floats
                int row = q >> 3, oc = q & 7;
                const float4* p = reinterpret_cast<const float4*>(
                    x + (size_t)(tok0 + row) * DDIM + t * TILEK + oc * 8);
                float4 f0 = p[0], f1 = p[1];
                const float fp[8] = {f0.x, f0.y, f0.z, f0.w, f1.x, f1.y, f1.z, f1.w};
                uint4 hv, lv;
                uint32_t* hw = reinterpret_cast<uint32_t*>(&hv);
                uint32_t* lw = reinterpret_cast<uint32_t*>(&lv);
                #pragma unroll
                for (int e = 0; e < 4; e++) {
                    float a = fp[2 * e], b = fp[2 * e + 1];
                    __nv_bfloat16 ah = __float2bfloat16(a), bh = __float2bfloat16(b);
                    float al = a - __bfloat162float(ah);
                    float bl = b - __bfloat162float(bh);
                    __nv_bfloat162 hp = __halves2bfloat162(ah, bh);
                    __nv_bfloat162 lp = __floats2bfloat162_rn(al, bl);
                    hw[e] = *reinterpret_cast<uint32_t*>(&hp);
                    lw[e] = *reinterpret_cast<uint32_t*>(&lp);
                }
                uint32_t off = SW128((uint32_t)(row * 128 + oc * 16));
                STS128(xb + off,           hv);
                STS128(xb + XLO_REL + off, lv);
            }
            CP_WAIT0();
            MBAR_ARRIVE(sb + (s ? BAR_FULL1 : BAR_FULL0));
        }
    }

    __syncthreads();   // pipeline done; smem free for epilogue

    // ---------------- epilogue ----------------
    float* epi = reinterpret_cast<float*>(smem + EPI_OFF);
    if (wid < 8) {
        const int WT    = (wid & 1) * 64;
        const int nbase = (wid >> 1) * 48;
        const int rg  = lane >> 2;
        const int cp2 = (lane & 3) * 2;
        #pragma unroll
        for (int mt = 0; mt < 4; mt++)
            #pragma unroll
            for (int nt = 0; nt < 6; nt++) {
                int r0 = WT + mt * 16 + rg;
                int c0 = nbase + nt * 8 + cp2;
                epi[r0 * EPI_PITCH + c0]           = acc[mt][nt][0];
                epi[r0 * EPI_PITCH + c0 + 1]       = acc[mt][nt][1];
                epi[(r0 + 8) * EPI_PITCH + c0]     = acc[mt][nt][2];
                epi[(r0 + 8) * EPI_PITCH + c0 + 1] = acc[mt][nt][3];
            }
    }
    __syncthreads();

    if (tid < MTOK) {
        const float* row = epi + tid * EPI_PITCH;
        const float asig = 1.f / (1.f + __expf(-alpha[0]));
        float v[64], g[64];

        #pragma unroll
        for (int i = 0; i < 64; i++)
            g[i] = 1.f / (1.f + __expf(-(row[128 + i] + biass[128 + i])));
        #pragma unroll
        for (int i = 0; i < 64; i++) v[i] = row[i] + biass[i];

        float m0 = v[0];
        #pragma unroll
        for (int i = 1; i < 64; i++) m0 = fmaxf(m0, v[i]);
        float prev = m0;
        for (int it = 0; it < 7; ++it) {
            float m = -3.4e38f;
            #pragma unroll
            for (int i = 0; i < 64; i++) {
                float c = (v[i] < prev) ? v[i] : -3.4e38f;
                m = fmaxf(m, c);
            }
            prev = m;
        }
        float tn = 0.f, td = 0.f;
        #pragma unroll
        for (int i = 0; i < 64; i++) {
            if (v[i] >= prev) {
                float e = __expf(v[i] - m0);
                tn += e * g[i]; td += e;
            }
        }

        #pragma unroll
        for (int i = 0; i < 64; i++) v[i] = row[64 + i] + biass[64 + i];
        float mf = v[0];
        #pragma unroll
        for (int i = 1; i < 64; i++) mf = fmaxf(mf, v[i]);
        float fn = 0.f, fd = 0.f;
        #pragma unroll
        for (int i = 0; i < 64; i++) {
            float e = __expf(v[i] - mf);
            fn += e * g[i]; fd += e;
        }

        out[tok0 + tid] = asig * (tn / td) + (1.f - asig) * (fn / fd);
    }
}

extern "C" void kernel_launch(void* const* d_in, const int* in_sizes, int n_in,
                              void* d_out, int out_size) {
    const float* x  = (const float*)d_in[0];
    const float* Wt = (const float*)d_in[1];
    const float* bt = (const float*)d_in[2];
    const float* Wf = (const float*)d_in[3];
    const float* bf = (const float*)d_in[4];
    const float* Wg = (const float*)d_in[5];
    const float* bg = (const float*)d_in[6];
    const float* al = (const float*)d_in[7];
    float* out = (float*)d_out;

    cudaFuncSetAttribute(moe_gate_main,
                         cudaFuncAttributeMaxDynamicSharedMemorySize, SMEM_BYTES);
    prep_w<<<NOUTS * DDIM / 256, 256>>>(Wt, Wf, Wg);
    moe_gate_main<<<NTOKENS / MTOK, 320, SMEM_BYTES>>>(x, bt, bf, bg, al, out);
}